// round 16
// baseline (speedup 1.0000x reference)
#include <cuda_runtime.h>
#include <cuda_fp16.h>
#include <cstdint>
#include <math.h>

#define LSEQ 4680
#define DIM  1536
#define NH   12
#define HD   128

// fp32 scratch
__device__ float g_q[LSEQ * DIM];
__device__ float g_k[LSEQ * DIM];
__device__ float g_v[LSEQ * DIM];

// split fp16 operands (16B alignment for cp.async)
__device__ __align__(256) __half g_xhi[LSEQ * DIM];
__device__ __align__(256) __half g_xlo[LSEQ * DIM];
__device__ __align__(256) __half g_ohi[LSEQ * DIM];
__device__ __align__(256) __half g_olo[LSEQ * DIM];
// weights: hi only
__device__ __align__(256) __half g_wqhi[DIM * DIM];
__device__ __align__(256) __half g_wkhi[DIM * DIM];
__device__ __align__(256) __half g_wvhi[DIM * DIM];
__device__ __align__(256) __half g_wohi[DIM * DIM];

// attention operands: Q hi (scaled, log2-space), K hi, V transposed hi
__device__ __align__(256) __half g_qhi[LSEQ * DIM];
__device__ __align__(256) __half g_khi[LSEQ * DIM];
__device__ __align__(256) __half g_vthi[DIM * LSEQ + 64];

// ---------------------------------------------------------------------------
// vectorized splits (n2 = n/2 float2 elements)
// ---------------------------------------------------------------------------
__global__ __launch_bounds__(256)
void split_kern(const float* __restrict__ in, __half* __restrict__ hi,
                __half* __restrict__ lo, int n2)
{
    int i = blockIdx.x * 256 + threadIdx.x;
    if (i < n2) {
        float2 a = ((const float2*)in)[i];
        __half h0 = __float2half_rn(a.x), h1 = __float2half_rn(a.y);
        __half2 hh; hh.x = h0; hh.y = h1;
        ((__half2*)hi)[i] = hh;
        __half2 ll;
        ll.x = __float2half_rn(a.x - __half2float(h0));
        ll.y = __float2half_rn(a.y - __half2float(h1));
        ((__half2*)lo)[i] = ll;
    }
}
// fused hi-only split for the 4 weight matrices (one launch)
__global__ __launch_bounds__(256)
void split_hi4_kern(const float* __restrict__ w0, const float* __restrict__ w1,
                    const float* __restrict__ w2, const float* __restrict__ w3,
                    __half* __restrict__ h0, __half* __restrict__ h1,
                    __half* __restrict__ h2, __half* __restrict__ h3, int n2)
{
    int i = blockIdx.x * 256 + threadIdx.x;
    if (i < 4 * n2) {
        int sel = i / n2, j = i - sel * n2;
        const float* src = (sel == 0) ? w0 : (sel == 1) ? w1 : (sel == 2) ? w2 : w3;
        __half* dst = (sel == 0) ? h0 : (sel == 1) ? h1 : (sel == 2) ? h2 : h3;
        float2 a = ((const float2*)src)[j];
        ((__half2*)dst)[j] = __floats2half2_rn(a.x, a.y);
    }
}

// ---------------------------------------------------------------------------
// helpers
// ---------------------------------------------------------------------------
__device__ __forceinline__ void ldsm4(uint32_t a, uint32_t& r0, uint32_t& r1,
                                      uint32_t& r2, uint32_t& r3)
{
    asm volatile("ldmatrix.sync.aligned.m8n8.x4.shared.b16 {%0,%1,%2,%3},[%4];\n"
                 : "=r"(r0), "=r"(r1), "=r"(r2), "=r"(r3) : "r"(a));
}
__device__ __forceinline__ void mma16816(float* c, const uint32_t* a, const uint32_t* b)
{
    asm volatile("mma.sync.aligned.m16n8k16.row.col.f32.f16.f16.f32 "
                 "{%0,%1,%2,%3},{%4,%5,%6,%7},{%8,%9},{%0,%1,%2,%3};\n"
                 : "+f"(c[0]), "+f"(c[1]), "+f"(c[2]), "+f"(c[3])
                 : "r"(a[0]), "r"(a[1]), "r"(a[2]), "r"(a[3]), "r"(b[0]), "r"(b[1]));
}
__device__ __forceinline__ void cp16(uint32_t dst, const void* src)
{
    asm volatile("cp.async.cg.shared.global [%0],[%1],16;\n" :: "r"(dst), "l"(src));
}
__device__ __forceinline__ uint32_t f2h2(float a, float b)
{
    __half2 h = __floats2half2_rn(a, b);
    return *(uint32_t*)&h;
}

// ---------------------------------------------------------------------------
// GEMM: C = A @ W^T + bias, 2-term split (Ahi+Alo)*Whi.
// Block 128x128, BK=32, 8 warps, **3-stage** cp.async pipeline, 2 CTA/SM.
// smem/stage 24KB -> 72KB total.
// ---------------------------------------------------------------------------
__global__ __launch_bounds__(256, 2)
void gemm_mma(const __half* __restrict__ Ahi, const __half* __restrict__ Alo,
              const __half* __restrict__ Whi,
              const float* __restrict__ bias, float* __restrict__ C, int M)
{
    const int N = DIM, K = DIM;
    extern __shared__ char smbuf[];
    uint32_t sbase = (uint32_t)__cvta_generic_to_shared(smbuf);
    int tid = threadIdx.x;
    int lane = tid & 31, warp = tid >> 5;
    int wm = warp & 1, wn = warp >> 1;
    int row0 = blockIdx.y * 128, col0 = blockIdx.x * 128;

    float acc[4][4][4];
#pragma unroll
    for (int mt = 0; mt < 4; mt++)
#pragma unroll
        for (int nt = 0; nt < 4; nt++)
#pragma unroll
            for (int i = 0; i < 4; i++) acc[mt][nt][i] = 0.f;

    int ld_row0 = tid >> 2, ld_ch0 = tid & 3;
    int ld_row1 = (tid + 256) >> 2, ld_ch1 = tid & 3;

#define LOAD_STAGE(s, kt)                                                          \
    do {                                                                           \
        int k0 = (kt) * 32;                                                        \
        uint32_t st = sbase + (s) * 24576;                                         \
        {                                                                          \
            int row = ld_row0, ch = ld_ch0;                                        \
            uint32_t off = row * 64 + ((ch ^ ((row >> 1) & 3)) << 4);              \
            int gr = row0 + row; if (gr > M - 1) gr = M - 1;                       \
            size_t aoff = (size_t)gr * K + k0 + ch * 8;                            \
            size_t boff = (size_t)(col0 + row) * K + k0 + ch * 8;                  \
            cp16(st + off,         Ahi + aoff);                                    \
            cp16(st + 8192 + off,  Alo + aoff);                                    \
            cp16(st + 16384 + off, Whi + boff);                                    \
        }                                                                          \
        {                                                                          \
            int row = ld_row1, ch = ld_ch1;                                        \
            uint32_t off = row * 64 + ((ch ^ ((row >> 1) & 3)) << 4);              \
            int gr = row0 + row; if (gr > M - 1) gr = M - 1;                       \
            size_t aoff = (size_t)gr * K + k0 + ch * 8;                            \
            size_t boff = (size_t)(col0 + row) * K + k0 + ch * 8;                  \
            cp16(st + off,         Ahi + aoff);                                    \
            cp16(st + 8192 + off,  Alo + aoff);                                    \
            cp16(st + 16384 + off, Whi + boff);                                    \
        }                                                                          \
        asm volatile("cp.async.commit_group;\n");                                  \
    } while (0)

    const int nk = K / 32;   // 48
    LOAD_STAGE(0, 0);
    LOAD_STAGE(1, 1);

    for (int kt = 0; kt < nk; kt++) {
        // issue load for kt+2 into buffer (kt+2)%3 (freed by compute kt-1,
        // protected by the trailing __syncthreads of iteration kt-1)
        if (kt + 2 < nk) {
            int s2 = kt + 2; s2 -= (s2 >= 3) ? ((s2 / 3) * 3) : 0;  // (kt+2)%3
            LOAD_STAGE((kt + 2) % 3, kt + 2);
            asm volatile("cp.async.wait_group 2;\n");
        } else if (kt + 1 < nk) {
            asm volatile("cp.async.wait_group 1;\n");
        } else {
            asm volatile("cp.async.wait_group 0;\n");
        }
        __syncthreads();
        uint32_t st = sbase + (kt % 3) * 24576;

#pragma unroll
        for (int ks = 0; ks < 2; ks++) {
            uint32_t afh[4][4], afl[4][4], bf[4][2];
            int ar = lane & 15;
            int ach = ks * 2 + (lane >> 4);
#pragma unroll
            for (int mt = 0; mt < 4; mt++) {
                int row = wm * 64 + mt * 16 + ar;
                uint32_t addr = st + row * 64 + ((ach ^ ((row >> 1) & 3)) << 4);
                ldsm4(addr, afh[mt][0], afh[mt][1], afh[mt][2], afh[mt][3]);
            }
            int brr = (lane & 7) + ((lane & 16) ? 8 : 0);
            int bch = ks * 2 + ((lane >> 3) & 1);
#pragma unroll
            for (int nt2 = 0; nt2 < 2; nt2++) {
                int row = wn * 32 + nt2 * 16 + brr;
                uint32_t addr = st + 16384 + row * 64 + ((bch ^ ((row >> 1) & 3)) << 4);
                ldsm4(addr, bf[nt2 * 2][0], bf[nt2 * 2][1],
                      bf[nt2 * 2 + 1][0], bf[nt2 * 2 + 1][1]);
            }
#pragma unroll
            for (int mt = 0; mt < 4; mt++)
#pragma unroll
                for (int nt = 0; nt < 4; nt++)
                    mma16816(acc[mt][nt], afh[mt], bf[nt]);
#pragma unroll
            for (int mt = 0; mt < 4; mt++) {
                int row = wm * 64 + mt * 16 + ar;
                uint32_t addr = st + 8192 + row * 64 + ((ach ^ ((row >> 1) & 3)) << 4);
                ldsm4(addr, afl[mt][0], afl[mt][1], afl[mt][2], afl[mt][3]);
            }
#pragma unroll
            for (int mt = 0; mt < 4; mt++)
#pragma unroll
                for (int nt = 0; nt < 4; nt++)
                    mma16816(acc[mt][nt], afl[mt], bf[nt]);
        }
        __syncthreads();
    }
#undef LOAD_STAGE

#pragma unroll
    for (int mt = 0; mt < 4; mt++) {
        int gr0 = row0 + wm * 64 + mt * 16 + (lane >> 2);
#pragma unroll
        for (int nt = 0; nt < 4; nt++) {
            int gc = col0 + wn * 32 + nt * 8 + (lane & 3) * 2;
            float bb0 = bias[gc], bb1 = bias[gc + 1];
            if (gr0 < M) {
                float2 v; v.x = acc[mt][nt][0] + bb0; v.y = acc[mt][nt][1] + bb1;
                *(float2*)&C[(size_t)gr0 * N + gc] = v;
            }
            int gr1 = gr0 + 8;
            if (gr1 < M) {
                float2 v; v.x = acc[mt][nt][2] + bb0; v.y = acc[mt][nt][3] + bb1;
                *(float2*)&C[(size_t)gr1 * N + gc] = v;
            }
        }
    }
}

// ---------------------------------------------------------------------------
// Fused RMSNorm + RoPE -> Q hi (scaled by log2e/sqrt(d)), K hi
// ---------------------------------------------------------------------------
__global__ __launch_bounds__(256)
void norm_rope(const float* __restrict__ q, const float* __restrict__ k,
               __half* __restrict__ qhi, __half* __restrict__ khi,
               const float* __restrict__ gq, const float* __restrict__ gk,
               const float* __restrict__ freqs,
               const int* __restrict__ p_h, const int* __restrict__ p_w,
               const int* __restrict__ p_sf)
{
    int l = blockIdx.x;
    int tid = threadIdx.x;
    __shared__ float sq[DIM], sk[DIM];
    __shared__ float redq[256], redk[256];

    size_t base = (size_t)l * DIM;
    float ssq = 0.f, ssk = 0.f;
    for (int i = tid; i < DIM; i += 256) {
        float a = q[base + i], b = k[base + i];
        sq[i] = a; sk[i] = b;
        ssq += a * a; ssk += b * b;
    }
    redq[tid] = ssq; redk[tid] = ssk;
    __syncthreads();
    for (int s = 128; s > 0; s >>= 1) {
        if (tid < s) { redq[tid] += redq[tid + s]; redk[tid] += redk[tid + s]; }
        __syncthreads();
    }
    float rq = rsqrtf(redq[0] * (1.f / DIM) + 1e-6f);
    float rk = rsqrtf(redk[0] * (1.f / DIM) + 1e-6f);

    int h = *p_h, w = *p_w, sf = *p_sf;
    int hw = h * w;
    int fr = l / hw, rem = l - fr * hw;
    int rr = rem / w, cc = rem - rr * w;
    const int c  = HD / 2;
    const int c1 = c / 3;
    const int c0 = c - 2 * c1;
    const float scl = rsqrtf((float)HD) * 1.4426950408889634f;

    for (int p = tid; p < DIM / 2; p += 256) {
        int head = p >> 6;
        int i    = p & 63;
        int pos  = (i < c0) ? (sf + fr) : ((i < c0 + c1) ? rr : cc);
        float ang = freqs[pos * c + i];
        float cs = cosf(ang), sn = sinf(ang);
        int idx = head * HD + 2 * i;

        float qre = sq[idx] * rq * gq[idx];
        float qim = sq[idx + 1] * rq * gq[idx + 1];
        qhi[base + idx]     = __float2half_rn((qre * cs - qim * sn) * scl);
        qhi[base + idx + 1] = __float2half_rn((qre * sn + qim * cs) * scl);

        float kre = sk[idx] * rk * gk[idx];
        float kim = sk[idx + 1] * rk * gk[idx + 1];
        khi[base + idx]     = __float2half_rn(kre * cs - kim * sn);
        khi[base + idx + 1] = __float2half_rn(kre * sn + kim * cs);
    }
}

// ---------------------------------------------------------------------------
// V transpose (hi only)
// ---------------------------------------------------------------------------
__global__ __launch_bounds__(256)
void prep_vt(const float* __restrict__ v, __half* __restrict__ vthi)
{
    __shared__ float t[32][33];
    int c0 = blockIdx.y * 32;
    int s0 = blockIdx.x * 32;
    int x = threadIdx.x & 31, y = threadIdx.x >> 5;
#pragma unroll
    for (int i = y; i < 32; i += 8) {
        int s = s0 + i;
        t[i][x] = (s < LSEQ) ? v[(size_t)s * DIM + c0 + x] : 0.f;
    }
    __syncthreads();
#pragma unroll
    for (int i = y; i < 32; i += 8) {
        int d = c0 + i;
        int s = s0 + x;
        if (s < LSEQ)
            vthi[(size_t)d * LSEQ + s] = __float2half_rn(t[x][i]);
    }
}

// ---------------------------------------------------------------------------
// Tensor-core flash attention (R14 known-good): fixed-shift fp32-exp2 softmax
// (P = exp2f(s - 12); the 2^-12 cancels in O = sum(Pv)/sum(P)).
// Block: 64 queries x 1 head, 4 warps, 64-key tiles, 3 CTA/SM, double buffer.
// Epilogue writes split hi/lo fp16 (feeds O-projection directly).
// ---------------------------------------------------------------------------
__global__ __launch_bounds__(128, 3)
void attn_mma(const __half* __restrict__ qhi, const __half* __restrict__ khi,
              const __half* __restrict__ vthi,
              __half* __restrict__ ohi, __half* __restrict__ olo,
              const int* __restrict__ p_h, const int* __restrict__ p_w,
              const int* __restrict__ p_local, const int* __restrict__ p_sink)
{
    extern __shared__ char smema[];
    uint32_t sb = (uint32_t)__cvta_generic_to_shared(smema);
    int tid = threadIdx.x, lane = tid & 31, warp = tid >> 5;
    int qb = blockIdx.x;
    int head = blockIdx.y;
    int r = lane >> 2, cg = lane & 3;

    int hw = (*p_h) * (*p_w);
    int local = *p_local, sink = *p_sink;

    int q0 = qb * 64 + warp * 16;
    int qrow0 = q0 + r, qrow1 = q0 + r + 8;
    int qc0 = min(qrow0, LSEQ - 1), qc1 = min(qrow1, LSEQ - 1);
    int fi0 = qc0 / hw, fi1 = qc1 / hw;

    int r0hi  = sink * hw;
    int r1lo0 = max(0, fi0 - local + 1) * hw, r1hi0 = (fi0 + 1) * hw;
    int r1lo1 = max(0, fi1 - local + 1) * hw, r1hi1 = (fi1 + 1) * hw;

    uint32_t qh[8][4];
    {
        int cb = head * HD + cg * 2;
#pragma unroll
        for (int dc = 0; dc < 8; dc++) {
            int cc = cb + dc * 16;
            qh[dc][0] = *(const uint32_t*)&qhi[(size_t)qc0 * DIM + cc];
            qh[dc][1] = *(const uint32_t*)&qhi[(size_t)qc1 * DIM + cc];
            qh[dc][2] = *(const uint32_t*)&qhi[(size_t)qc0 * DIM + cc + 8];
            qh[dc][3] = *(const uint32_t*)&qhi[(size_t)qc1 * DIM + cc + 8];
        }
    }

    float l0 = 0.f, l1 = 0.f;
    float oacc[16][4];
#pragma unroll
    for (int nt = 0; nt < 16; nt++)
#pragma unroll
        for (int i = 0; i < 4; i++) oacc[nt][i] = 0.f;

    int krow = tid >> 1;
    int kc0  = (tid & 1) * 8;
    int vrow = tid;

    int qlast = min(qb * 64 + 63, LSEQ - 1);
    int kend = (qlast / hw + 1) * hw;
    int ntiles = (kend + 63) / 64;

    int g = lane >> 3, lr = lane & 7;

#define ALOAD(stage, kt)                                                         \
    do {                                                                         \
        int kb_ = (kt) * 64;                                                     \
        uint32_t st_ = sb + (stage) * 32768;                                     \
        int krg = min(kb_ + krow, LSEQ - 1);                                     \
        size_t kgb = (size_t)krg * DIM + head * HD;                              \
        _Pragma("unroll")                                                        \
        for (int j = 0; j < 8; j++) {                                            \
            int ch = kc0 + j;                                                    \
            uint32_t off = krow * 256 + ((ch ^ (krow & 7)) << 4);                \
            cp16(st_ + off, khi + kgb + ch * 8);                                 \
        }                                                                        \
        size_t vgb = (size_t)(head * HD + vrow) * LSEQ + kb_;                    \
        _Pragma("unroll")                                                        \
        for (int ch = 0; ch < 8; ch++) {                                         \
            uint32_t off = vrow * 128 + ((ch ^ (vrow & 7)) << 4);                \
            cp16(st_ + 16384 + off, vthi + vgb + ch * 8);                        \
        }                                                                        \
        asm volatile("cp.async.commit_group;\n");                                \
    } while (0)

    ALOAD(0, 0);

    for (int kt = 0; kt < ntiles; kt++) {
        int kb = kt * 64;
        if (kt + 1 < ntiles) {
            ALOAD((kt + 1) & 1, kt + 1);
            asm volatile("cp.async.wait_group 1;\n");
        } else {
            asm volatile("cp.async.wait_group 0;\n");
        }
        __syncthreads();
        uint32_t KHI = sb + (kt & 1) * 32768;
        uint32_t VHI = KHI + 16384;

        // ---- QK^T (single term) ----
        float s[8][4];
#pragma unroll
        for (int nt = 0; nt < 8; nt++)
#pragma unroll
            for (int i = 0; i < 4; i++) s[nt][i] = 0.f;

#pragma unroll
        for (int dc = 0; dc < 8; dc++) {
            int ch = 2 * dc + (g & 1);
#pragma unroll
            for (int np = 0; np < 4; np++) {
                int row = np * 16 + ((g >> 1) << 3) + lr;
                uint32_t addr = KHI + row * 256 + ((ch ^ (row & 7)) << 4);
                uint32_t bh0[2], bh1[2];
                ldsm4(addr, bh0[0], bh0[1], bh1[0], bh1[1]);
                mma16816(s[np * 2],     qh[dc], bh0);
                mma16816(s[np * 2 + 1], qh[dc], bh1);
            }
        }

        // ---- mask + fixed-shift softmax: P = exp2f(s - 12) ----
        const float SHIFT = 12.f;
        float ps0 = 0.f, ps1 = 0.f;
        uint32_t pa[4][4];
#pragma unroll
        for (int nt = 0; nt < 8; nt++) {
            int lk0 = kb + nt * 8 + cg * 2;
            int lk1 = lk0 + 1;
            bool okA0 = (lk0 < r1hi0) && ((lk0 >= r1lo0) || (lk0 < r0hi));
            bool okB0 = (lk1 < r1hi0) && ((lk1 >= r1lo0) || (lk1 < r0hi));
            bool okA1 = (lk0 < r1hi1) && ((lk0 >= r1lo1) || (lk0 < r0hi));
            bool okB1 = (lk1 < r1hi1) && ((lk1 >= r1lo1) || (lk1 < r0hi));
            float p0 = okA0 ? exp2f(s[nt][0] - SHIFT) : 0.f;
            float p1 = okB0 ? exp2f(s[nt][1] - SHIFT) : 0.f;
            float p2 = okA1 ? exp2f(s[nt][2] - SHIFT) : 0.f;
            float p3 = okB1 ? exp2f(s[nt][3] - SHIFT) : 0.f;
            ps0 += p0 + p1; ps1 += p2 + p3;
            s[nt][0] = p0; s[nt][1] = p1; s[nt][2] = p2; s[nt][3] = p3;
        }
        l0 += ps0; l1 += ps1;

#pragma unroll
        for (int kp = 0; kp < 4; kp++) {
            pa[kp][0] = f2h2(s[2 * kp][0],     s[2 * kp][1]);
            pa[kp][1] = f2h2(s[2 * kp][2],     s[2 * kp][3]);
            pa[kp][2] = f2h2(s[2 * kp + 1][0], s[2 * kp + 1][1]);
            pa[kp][3] = f2h2(s[2 * kp + 1][2], s[2 * kp + 1][3]);
        }

        // ---- P @ V (single term) ----
#pragma unroll
        for (int kp = 0; kp < 4; kp++) {
            int ch = 2 * kp + (g & 1);
#pragma unroll
            for (int dp = 0; dp < 8; dp++) {
                int row = dp * 16 + ((g >> 1) << 3) + lr;
                uint32_t addr = VHI + row * 128 + ((ch ^ (row & 7)) << 4);
                uint32_t bh0[2], bh1[2];
                ldsm4(addr, bh0[0], bh0[1], bh1[0], bh1[1]);
                mma16816(oacc[dp * 2],     pa[kp], bh0);
                mma16816(oacc[dp * 2 + 1], pa[kp], bh1);
            }
        }
        __syncthreads();
    }
#undef ALOAD

    l0 += __shfl_xor_sync(0xffffffffu, l0, 1);
    l0 += __shfl_xor_sync(0xffffffffu, l0, 2);
    l1 += __shfl_xor_sync(0xffffffffu, l1, 1);
    l1 += __shfl_xor_sync(0xffffffffu, l1, 2);
    float inv0 = 1.f / l0, inv1 = 1.f / l1;

    // epilogue: write split hi/lo fp16 directly (consumed by O-projection)
#pragma unroll
    for (int nt = 0; nt < 16; nt++) {
        int col = head * HD + nt * 8 + cg * 2;
        if (qrow0 < LSEQ) {
            float v0 = oacc[nt][0] * inv0, v1 = oacc[nt][1] * inv0;
            __half h0 = __float2half_rn(v0), h1 = __float2half_rn(v1);
            size_t off = (size_t)qrow0 * DIM + col;
            *(uint32_t*)&ohi[off] = f2h2(v0, v1);
            *(uint32_t*)&olo[off] = f2h2(v0 - __half2float(h0), v1 - __half2float(h1));
        }
        if (qrow1 < LSEQ) {
            float v0 = oacc[nt][2] * inv1, v1 = oacc[nt][3] * inv1;
            __half h0 = __float2half_rn(v0), h1 = __float2half_rn(v1);
            size_t off = (size_t)qrow1 * DIM + col;
            *(uint32_t*)&ohi[off] = f2h2(v0, v1);
            *(uint32_t*)&olo[off] = f2h2(v0 - __half2float(h0), v1 - __half2float(h1));
        }
    }
}

// ---------------------------------------------------------------------------
extern "C" void kernel_launch(void* const* d_in, const int* in_sizes, int n_in,
                              void* d_out, int out_size)
{
    const float* x     = (const float*)d_in[0];
    const float* freqs = (const float*)d_in[1];
    const float* Wq    = (const float*)d_in[2];
    const float* bq    = (const float*)d_in[3];
    const float* Wk    = (const float*)d_in[4];
    const float* bk    = (const float*)d_in[5];
    const float* Wv    = (const float*)d_in[6];
    const float* bv    = (const float*)d_in[7];
    const float* Wo    = (const float*)d_in[8];
    const float* bo    = (const float*)d_in[9];
    const float* gq    = (const float*)d_in[10];
    const float* gk    = (const float*)d_in[11];
    const int* p_h     = (const int*)d_in[13];
    const int* p_w     = (const int*)d_in[14];
    const int* p_local = (const int*)d_in[16];
    const int* p_sink  = (const int*)d_in[17];
    const int* p_sf    = (const int*)d_in[18];
    float* out = (float*)d_out;
    (void)in_sizes; (void)n_in; (void)out_size;

    float *pq, *pk, *pv;
    cudaGetSymbolAddress((void**)&pq, g_q);
    cudaGetSymbolAddress((void**)&pk, g_k);
    cudaGetSymbolAddress((void**)&pv, g_v);

    __half *xhi, *xlo, *ohi, *olo;
    __half *wqhi, *wkhi, *wvhi, *wohi;
    __half *aqhi, *akhi, *vthi;
    cudaGetSymbolAddress((void**)&xhi, g_xhi);
    cudaGetSymbolAddress((void**)&xlo, g_xlo);
    cudaGetSymbolAddress((void**)&ohi, g_ohi);
    cudaGetSymbolAddress((void**)&olo, g_olo);
    cudaGetSymbolAddress((void**)&wqhi, g_wqhi);
    cudaGetSymbolAddress((void**)&wkhi, g_wkhi);
    cudaGetSymbolAddress((void**)&wvhi, g_wvhi);
    cudaGetSymbolAddress((void**)&wohi, g_wohi);
    cudaGetSymbolAddress((void**)&aqhi, g_qhi);
    cudaGetSymbolAddress((void**)&akhi, g_khi);
    cudaGetSymbolAddress((void**)&vthi, g_vthi);

    const int GEMM_SMEM = 3 * 24576;   // 72 KB (3-stage)
    const int ATTN_SMEM = 2 * 32768;   // 64 KB
    cudaFuncSetAttribute(gemm_mma, cudaFuncAttributeMaxDynamicSharedMemorySize, GEMM_SMEM);
    cudaFuncSetAttribute(attn_mma, cudaFuncAttributeMaxDynamicSharedMemorySize, ATTN_SMEM);

    const int nx2 = LSEQ * DIM / 2, nw2 = DIM * DIM / 2;
    split_kern<<<(nx2 + 255) / 256, 256>>>(x, xhi, xlo, nx2);
    split_hi4_kern<<<(4 * nw2 + 255) / 256, 256>>>(Wq, Wk, Wv, Wo,
                                                   wqhi, wkhi, wvhi, wohi, nw2);

    dim3 gg(DIM / 128, (LSEQ + 127) / 128);
    gemm_mma<<<gg, 256, GEMM_SMEM>>>(xhi, xlo, wqhi, bq, pq, LSEQ);
    gemm_mma<<<gg, 256, GEMM_SMEM>>>(xhi, xlo, wkhi, bk, pk, LSEQ);
    gemm_mma<<<gg, 256, GEMM_SMEM>>>(xhi, xlo, wvhi, bv, pv, LSEQ);

    norm_rope<<<LSEQ, 256>>>(pq, pk, aqhi, akhi, gq, gk, freqs,
                             p_h, p_w, p_sf);
    prep_vt<<<dim3((LSEQ + 31) / 32, DIM / 32), 256>>>(pv, vthi);

    attn_mma<<<dim3((LSEQ + 63) / 64, NH), 128, ATTN_SMEM>>>(
        aqhi, akhi, vthi, ohi, olo, p_h, p_w, p_local, p_sink);

    gemm_mma<<<gg, 256, GEMM_SMEM>>>(ohi, olo, wohi, bo, out, LSEQ);
}

// round 17
// speedup vs baseline: 1.0469x; 1.0469x over previous
#include <cuda_runtime.h>
#include <cuda_fp16.h>
#include <cstdint>
#include <math.h>

#define LSEQ 4680
#define DIM  1536
#define NH   12
#define HD   128

// fp32 scratch
__device__ float g_q[LSEQ * DIM];
__device__ float g_k[LSEQ * DIM];
__device__ float g_v[LSEQ * DIM];

// split fp16 operands (16B alignment for cp.async)
__device__ __align__(256) __half g_xhi[LSEQ * DIM];
__device__ __align__(256) __half g_xlo[LSEQ * DIM];
__device__ __align__(256) __half g_ohi[LSEQ * DIM];
__device__ __align__(256) __half g_olo[LSEQ * DIM];
// weights: hi only
__device__ __align__(256) __half g_wqhi[DIM * DIM];
__device__ __align__(256) __half g_wkhi[DIM * DIM];
__device__ __align__(256) __half g_wvhi[DIM * DIM];
__device__ __align__(256) __half g_wohi[DIM * DIM];

// attention operands: Q hi (scaled, log2-space), K hi, V transposed hi
__device__ __align__(256) __half g_qhi[LSEQ * DIM];
__device__ __align__(256) __half g_khi[LSEQ * DIM];
__device__ __align__(256) __half g_vthi[DIM * LSEQ + 64];

// ---------------------------------------------------------------------------
// vectorized splits (n2 = n/2 float2 elements)
// ---------------------------------------------------------------------------
__global__ __launch_bounds__(256)
void split_kern(const float* __restrict__ in, __half* __restrict__ hi,
                __half* __restrict__ lo, int n2)
{
    int i = blockIdx.x * 256 + threadIdx.x;
    if (i < n2) {
        float2 a = ((const float2*)in)[i];
        __half h0 = __float2half_rn(a.x), h1 = __float2half_rn(a.y);
        __half2 hh; hh.x = h0; hh.y = h1;
        ((__half2*)hi)[i] = hh;
        __half2 ll;
        ll.x = __float2half_rn(a.x - __half2float(h0));
        ll.y = __float2half_rn(a.y - __half2float(h1));
        ((__half2*)lo)[i] = ll;
    }
}
// fused hi-only split for the 4 weight matrices (one launch)
__global__ __launch_bounds__(256)
void split_hi4_kern(const float* __restrict__ w0, const float* __restrict__ w1,
                    const float* __restrict__ w2, const float* __restrict__ w3,
                    __half* __restrict__ h0, __half* __restrict__ h1,
                    __half* __restrict__ h2, __half* __restrict__ h3, int n2)
{
    int i = blockIdx.x * 256 + threadIdx.x;
    if (i < 4 * n2) {
        int sel = i / n2, j = i - sel * n2;
        const float* src = (sel == 0) ? w0 : (sel == 1) ? w1 : (sel == 2) ? w2 : w3;
        __half* dst = (sel == 0) ? h0 : (sel == 1) ? h1 : (sel == 2) ? h2 : h3;
        float2 a = ((const float2*)src)[j];
        ((__half2*)dst)[j] = __floats2half2_rn(a.x, a.y);
    }
}

// ---------------------------------------------------------------------------
// helpers
// ---------------------------------------------------------------------------
__device__ __forceinline__ void ldsm4(uint32_t a, uint32_t& r0, uint32_t& r1,
                                      uint32_t& r2, uint32_t& r3)
{
    asm volatile("ldmatrix.sync.aligned.m8n8.x4.shared.b16 {%0,%1,%2,%3},[%4];\n"
                 : "=r"(r0), "=r"(r1), "=r"(r2), "=r"(r3) : "r"(a));
}
__device__ __forceinline__ void mma16816(float* c, const uint32_t* a, const uint32_t* b)
{
    asm volatile("mma.sync.aligned.m16n8k16.row.col.f32.f16.f16.f32 "
                 "{%0,%1,%2,%3},{%4,%5,%6,%7},{%8,%9},{%0,%1,%2,%3};\n"
                 : "+f"(c[0]), "+f"(c[1]), "+f"(c[2]), "+f"(c[3])
                 : "r"(a[0]), "r"(a[1]), "r"(a[2]), "r"(a[3]), "r"(b[0]), "r"(b[1]));
}
__device__ __forceinline__ void cp16(uint32_t dst, const void* src)
{
    asm volatile("cp.async.cg.shared.global [%0],[%1],16;\n" :: "r"(dst), "l"(src));
}
__device__ __forceinline__ uint32_t f2h2(float a, float b)
{
    __half2 h = __floats2half2_rn(a, b);
    return *(uint32_t*)&h;
}

// ---------------------------------------------------------------------------
// GEMM: C = A @ W^T + bias, 2-term split (Ahi+Alo)*Whi.
// Block 128x128, BK=32, 8 warps, 2-stage cp.async, 2 CTA/SM.
// SINGLE barrier per K-chunk: the next-stage load is issued after the leading
// barrier, so the buffer it overwrites (last read in chunk kt-1) is already
// released by every warp.
// ---------------------------------------------------------------------------
__global__ __launch_bounds__(256, 2)
void gemm_mma(const __half* __restrict__ Ahi, const __half* __restrict__ Alo,
              const __half* __restrict__ Whi,
              const float* __restrict__ bias, float* __restrict__ C, int M)
{
    const int N = DIM, K = DIM;
    extern __shared__ char smbuf[];
    uint32_t sbase = (uint32_t)__cvta_generic_to_shared(smbuf);
    int tid = threadIdx.x;
    int lane = tid & 31, warp = tid >> 5;
    int wm = warp & 1, wn = warp >> 1;
    int row0 = blockIdx.y * 128, col0 = blockIdx.x * 128;

    float acc[4][4][4];
#pragma unroll
    for (int mt = 0; mt < 4; mt++)
#pragma unroll
        for (int nt = 0; nt < 4; nt++)
#pragma unroll
            for (int i = 0; i < 4; i++) acc[mt][nt][i] = 0.f;

    int ld_row0 = tid >> 2, ld_ch0 = tid & 3;
    int ld_row1 = (tid + 256) >> 2, ld_ch1 = tid & 3;

#define LOAD_STAGE(s, kt)                                                          \
    do {                                                                           \
        int k0 = (kt) * 32;                                                        \
        uint32_t st = sbase + (s) * 24576;                                         \
        {                                                                          \
            int row = ld_row0, ch = ld_ch0;                                        \
            uint32_t off = row * 64 + ((ch ^ ((row >> 1) & 3)) << 4);              \
            int gr = row0 + row; if (gr > M - 1) gr = M - 1;                       \
            size_t aoff = (size_t)gr * K + k0 + ch * 8;                            \
            size_t boff = (size_t)(col0 + row) * K + k0 + ch * 8;                  \
            cp16(st + off,         Ahi + aoff);                                    \
            cp16(st + 8192 + off,  Alo + aoff);                                    \
            cp16(st + 16384 + off, Whi + boff);                                    \
        }                                                                          \
        {                                                                          \
            int row = ld_row1, ch = ld_ch1;                                        \
            uint32_t off = row * 64 + ((ch ^ ((row >> 1) & 3)) << 4);              \
            int gr = row0 + row; if (gr > M - 1) gr = M - 1;                       \
            size_t aoff = (size_t)gr * K + k0 + ch * 8;                            \
            size_t boff = (size_t)(col0 + row) * K + k0 + ch * 8;                  \
            cp16(st + off,         Ahi + aoff);                                    \
            cp16(st + 8192 + off,  Alo + aoff);                                    \
            cp16(st + 16384 + off, Whi + boff);                                    \
        }                                                                          \
        asm volatile("cp.async.commit_group;\n");                                  \
    } while (0)

    LOAD_STAGE(0, 0);
    const int nk = K / 32;
    for (int kt = 0; kt < nk; kt++) {
        asm volatile("cp.async.wait_group 0;\n");
        __syncthreads();
        if (kt + 1 < nk) LOAD_STAGE((kt + 1) & 1, kt + 1);
        uint32_t st = sbase + (kt & 1) * 24576;

#pragma unroll
        for (int ks = 0; ks < 2; ks++) {
            uint32_t afh[4][4], afl[4][4], bf[4][2];
            int ar = lane & 15;
            int ach = ks * 2 + (lane >> 4);
#pragma unroll
            for (int mt = 0; mt < 4; mt++) {
                int row = wm * 64 + mt * 16 + ar;
                uint32_t addr = st + row * 64 + ((ach ^ ((row >> 1) & 3)) << 4);
                ldsm4(addr, afh[mt][0], afh[mt][1], afh[mt][2], afh[mt][3]);
            }
            int brr = (lane & 7) + ((lane & 16) ? 8 : 0);
            int bch = ks * 2 + ((lane >> 3) & 1);
#pragma unroll
            for (int nt2 = 0; nt2 < 2; nt2++) {
                int row = wn * 32 + nt2 * 16 + brr;
                uint32_t addr = st + 16384 + row * 64 + ((bch ^ ((row >> 1) & 3)) << 4);
                ldsm4(addr, bf[nt2 * 2][0], bf[nt2 * 2][1],
                      bf[nt2 * 2 + 1][0], bf[nt2 * 2 + 1][1]);
            }
#pragma unroll
            for (int mt = 0; mt < 4; mt++)
#pragma unroll
                for (int nt = 0; nt < 4; nt++)
                    mma16816(acc[mt][nt], afh[mt], bf[nt]);
#pragma unroll
            for (int mt = 0; mt < 4; mt++) {
                int row = wm * 64 + mt * 16 + ar;
                uint32_t addr = st + 8192 + row * 64 + ((ach ^ ((row >> 1) & 3)) << 4);
                ldsm4(addr, afl[mt][0], afl[mt][1], afl[mt][2], afl[mt][3]);
            }
#pragma unroll
            for (int mt = 0; mt < 4; mt++)
#pragma unroll
                for (int nt = 0; nt < 4; nt++)
                    mma16816(acc[mt][nt], afl[mt], bf[nt]);
        }
        // no trailing barrier: next iteration's leading barrier provides the
        // release point before buffer (kt+1)&1 is overwritten.
    }
#undef LOAD_STAGE

#pragma unroll
    for (int mt = 0; mt < 4; mt++) {
        int gr0 = row0 + wm * 64 + mt * 16 + (lane >> 2);
#pragma unroll
        for (int nt = 0; nt < 4; nt++) {
            int gc = col0 + wn * 32 + nt * 8 + (lane & 3) * 2;
            float bb0 = bias[gc], bb1 = bias[gc + 1];
            if (gr0 < M) {
                float2 v; v.x = acc[mt][nt][0] + bb0; v.y = acc[mt][nt][1] + bb1;
                *(float2*)&C[(size_t)gr0 * N + gc] = v;
            }
            int gr1 = gr0 + 8;
            if (gr1 < M) {
                float2 v; v.x = acc[mt][nt][2] + bb0; v.y = acc[mt][nt][3] + bb1;
                *(float2*)&C[(size_t)gr1 * N + gc] = v;
            }
        }
    }
}

// ---------------------------------------------------------------------------
// Fused RMSNorm + RoPE -> Q hi (scaled by log2e/sqrt(d)), K hi
// ---------------------------------------------------------------------------
__global__ __launch_bounds__(256)
void norm_rope(const float* __restrict__ q, const float* __restrict__ k,
               __half* __restrict__ qhi, __half* __restrict__ khi,
               const float* __restrict__ gq, const float* __restrict__ gk,
               const float* __restrict__ freqs,
               const int* __restrict__ p_h, const int* __restrict__ p_w,
               const int* __restrict__ p_sf)
{
    int l = blockIdx.x;
    int tid = threadIdx.x;
    __shared__ float sq[DIM], sk[DIM];
    __shared__ float redq[256], redk[256];

    size_t base = (size_t)l * DIM;
    float ssq = 0.f, ssk = 0.f;
    for (int i = tid; i < DIM; i += 256) {
        float a = q[base + i], b = k[base + i];
        sq[i] = a; sk[i] = b;
        ssq += a * a; ssk += b * b;
    }
    redq[tid] = ssq; redk[tid] = ssk;
    __syncthreads();
    for (int s = 128; s > 0; s >>= 1) {
        if (tid < s) { redq[tid] += redq[tid + s]; redk[tid] += redk[tid + s]; }
        __syncthreads();
    }
    float rq = rsqrtf(redq[0] * (1.f / DIM) + 1e-6f);
    float rk = rsqrtf(redk[0] * (1.f / DIM) + 1e-6f);

    int h = *p_h, w = *p_w, sf = *p_sf;
    int hw = h * w;
    int fr = l / hw, rem = l - fr * hw;
    int rr = rem / w, cc = rem - rr * w;
    const int c  = HD / 2;
    const int c1 = c / 3;
    const int c0 = c - 2 * c1;
    const float scl = rsqrtf((float)HD) * 1.4426950408889634f;

    for (int p = tid; p < DIM / 2; p += 256) {
        int head = p >> 6;
        int i    = p & 63;
        int pos  = (i < c0) ? (sf + fr) : ((i < c0 + c1) ? rr : cc);
        float ang = freqs[pos * c + i];
        float cs = cosf(ang), sn = sinf(ang);
        int idx = head * HD + 2 * i;

        float qre = sq[idx] * rq * gq[idx];
        float qim = sq[idx + 1] * rq * gq[idx + 1];
        qhi[base + idx]     = __float2half_rn((qre * cs - qim * sn) * scl);
        qhi[base + idx + 1] = __float2half_rn((qre * sn + qim * cs) * scl);

        float kre = sk[idx] * rk * gk[idx];
        float kim = sk[idx + 1] * rk * gk[idx + 1];
        khi[base + idx]     = __float2half_rn(kre * cs - kim * sn);
        khi[base + idx + 1] = __float2half_rn(kre * sn + kim * cs);
    }
}

// ---------------------------------------------------------------------------
// V transpose (hi only)
// ---------------------------------------------------------------------------
__global__ __launch_bounds__(256)
void prep_vt(const float* __restrict__ v, __half* __restrict__ vthi)
{
    __shared__ float t[32][33];
    int c0 = blockIdx.y * 32;
    int s0 = blockIdx.x * 32;
    int x = threadIdx.x & 31, y = threadIdx.x >> 5;
#pragma unroll
    for (int i = y; i < 32; i += 8) {
        int s = s0 + i;
        t[i][x] = (s < LSEQ) ? v[(size_t)s * DIM + c0 + x] : 0.f;
    }
    __syncthreads();
#pragma unroll
    for (int i = y; i < 32; i += 8) {
        int d = c0 + i;
        int s = s0 + x;
        if (s < LSEQ)
            vthi[(size_t)d * LSEQ + s] = __float2half_rn(t[x][i]);
    }
}

// ---------------------------------------------------------------------------
// Tensor-core flash attention: fixed-shift fp32-exp2 softmax,
// SINGLE barrier per KV tile (load issued after the barrier; buffer it
// overwrites was released by all warps at that barrier).
// Block: 64 queries x 1 head, 4 warps, 64-key tiles, 3 CTA/SM, double buffer.
// Epilogue writes split hi/lo fp16 (feeds O-projection directly).
// ---------------------------------------------------------------------------
__global__ __launch_bounds__(128, 3)
void attn_mma(const __half* __restrict__ qhi, const __half* __restrict__ khi,
              const __half* __restrict__ vthi,
              __half* __restrict__ ohi, __half* __restrict__ olo,
              const int* __restrict__ p_h, const int* __restrict__ p_w,
              const int* __restrict__ p_local, const int* __restrict__ p_sink)
{
    extern __shared__ char smema[];
    uint32_t sb = (uint32_t)__cvta_generic_to_shared(smema);
    int tid = threadIdx.x, lane = tid & 31, warp = tid >> 5;
    int qb = blockIdx.x;
    int head = blockIdx.y;
    int r = lane >> 2, cg = lane & 3;

    int hw = (*p_h) * (*p_w);
    int local = *p_local, sink = *p_sink;

    int q0 = qb * 64 + warp * 16;
    int qrow0 = q0 + r, qrow1 = q0 + r + 8;
    int qc0 = min(qrow0, LSEQ - 1), qc1 = min(qrow1, LSEQ - 1);
    int fi0 = qc0 / hw, fi1 = qc1 / hw;

    int r0hi  = sink * hw;
    int r1lo0 = max(0, fi0 - local + 1) * hw, r1hi0 = (fi0 + 1) * hw;
    int r1lo1 = max(0, fi1 - local + 1) * hw, r1hi1 = (fi1 + 1) * hw;

    uint32_t qh[8][4];
    {
        int cb = head * HD + cg * 2;
#pragma unroll
        for (int dc = 0; dc < 8; dc++) {
            int cc = cb + dc * 16;
            qh[dc][0] = *(const uint32_t*)&qhi[(size_t)qc0 * DIM + cc];
            qh[dc][1] = *(const uint32_t*)&qhi[(size_t)qc1 * DIM + cc];
            qh[dc][2] = *(const uint32_t*)&qhi[(size_t)qc0 * DIM + cc + 8];
            qh[dc][3] = *(const uint32_t*)&qhi[(size_t)qc1 * DIM + cc + 8];
        }
    }

    float l0 = 0.f, l1 = 0.f;
    float oacc[16][4];
#pragma unroll
    for (int nt = 0; nt < 16; nt++)
#pragma unroll
        for (int i = 0; i < 4; i++) oacc[nt][i] = 0.f;

    int krow = tid >> 1;
    int kc0  = (tid & 1) * 8;
    int vrow = tid;

    int qlast = min(qb * 64 + 63, LSEQ - 1);
    int kend = (qlast / hw + 1) * hw;
    int ntiles = (kend + 63) / 64;

    int g = lane >> 3, lr = lane & 7;

#define ALOAD(stage, kt)                                                         \
    do {                                                                         \
        int kb_ = (kt) * 64;                                                     \
        uint32_t st_ = sb + (stage) * 32768;                                     \
        int krg = min(kb_ + krow, LSEQ - 1);                                     \
        size_t kgb = (size_t)krg * DIM + head * HD;                              \
        _Pragma("unroll")                                                        \
        for (int j = 0; j < 8; j++) {                                            \
            int ch = kc0 + j;                                                    \
            uint32_t off = krow * 256 + ((ch ^ (krow & 7)) << 4);                \
            cp16(st_ + off, khi + kgb + ch * 8);                                 \
        }                                                                        \
        size_t vgb = (size_t)(head * HD + vrow) * LSEQ + kb_;                    \
        _Pragma("unroll")                                                        \
        for (int ch = 0; ch < 8; ch++) {                                         \
            uint32_t off = vrow * 128 + ((ch ^ (vrow & 7)) << 4);                \
            cp16(st_ + 16384 + off, vthi + vgb + ch * 8);                        \
        }                                                                        \
        asm volatile("cp.async.commit_group;\n");                                \
    } while (0)

    ALOAD(0, 0);

    for (int kt = 0; kt < ntiles; kt++) {
        int kb = kt * 64;
        asm volatile("cp.async.wait_group 0;\n");
        __syncthreads();
        if (kt + 1 < ntiles) ALOAD((kt + 1) & 1, kt + 1);
        uint32_t KHI = sb + (kt & 1) * 32768;
        uint32_t VHI = KHI + 16384;

        // ---- QK^T (single term) ----
        float s[8][4];
#pragma unroll
        for (int nt = 0; nt < 8; nt++)
#pragma unroll
            for (int i = 0; i < 4; i++) s[nt][i] = 0.f;

#pragma unroll
        for (int dc = 0; dc < 8; dc++) {
            int ch = 2 * dc + (g & 1);
#pragma unroll
            for (int np = 0; np < 4; np++) {
                int row = np * 16 + ((g >> 1) << 3) + lr;
                uint32_t addr = KHI + row * 256 + ((ch ^ (row & 7)) << 4);
                uint32_t bh0[2], bh1[2];
                ldsm4(addr, bh0[0], bh0[1], bh1[0], bh1[1]);
                mma16816(s[np * 2],     qh[dc], bh0);
                mma16816(s[np * 2 + 1], qh[dc], bh1);
            }
        }

        // ---- mask + fixed-shift softmax: P = exp2f(s - 12) ----
        const float SHIFT = 12.f;
        float ps0 = 0.f, ps1 = 0.f;
        uint32_t pa[4][4];
#pragma unroll
        for (int nt = 0; nt < 8; nt++) {
            int lk0 = kb + nt * 8 + cg * 2;
            int lk1 = lk0 + 1;
            bool okA0 = (lk0 < r1hi0) && ((lk0 >= r1lo0) || (lk0 < r0hi));
            bool okB0 = (lk1 < r1hi0) && ((lk1 >= r1lo0) || (lk1 < r0hi));
            bool okA1 = (lk0 < r1hi1) && ((lk0 >= r1lo1) || (lk0 < r0hi));
            bool okB1 = (lk1 < r1hi1) && ((lk1 >= r1lo1) || (lk1 < r0hi));
            float p0 = okA0 ? exp2f(s[nt][0] - SHIFT) : 0.f;
            float p1 = okB0 ? exp2f(s[nt][1] - SHIFT) : 0.f;
            float p2 = okA1 ? exp2f(s[nt][2] - SHIFT) : 0.f;
            float p3 = okB1 ? exp2f(s[nt][3] - SHIFT) : 0.f;
            ps0 += p0 + p1; ps1 += p2 + p3;
            s[nt][0] = p0; s[nt][1] = p1; s[nt][2] = p2; s[nt][3] = p3;
        }
        l0 += ps0; l1 += ps1;

#pragma unroll
        for (int kp = 0; kp < 4; kp++) {
            pa[kp][0] = f2h2(s[2 * kp][0],     s[2 * kp][1]);
            pa[kp][1] = f2h2(s[2 * kp][2],     s[2 * kp][3]);
            pa[kp][2] = f2h2(s[2 * kp + 1][0], s[2 * kp + 1][1]);
            pa[kp][3] = f2h2(s[2 * kp + 1][2], s[2 * kp + 1][3]);
        }

        // ---- P @ V (single term) ----
#pragma unroll
        for (int kp = 0; kp < 4; kp++) {
            int ch = 2 * kp + (g & 1);
#pragma unroll
            for (int dp = 0; dp < 8; dp++) {
                int row = dp * 16 + ((g >> 1) << 3) + lr;
                uint32_t addr = VHI + row * 128 + ((ch ^ (row & 7)) << 4);
                uint32_t bh0[2], bh1[2];
                ldsm4(addr, bh0[0], bh0[1], bh1[0], bh1[1]);
                mma16816(oacc[dp * 2],     pa[kp], bh0);
                mma16816(oacc[dp * 2 + 1], pa[kp], bh1);
            }
        }
        // no trailing barrier: next iteration's leading barrier is the
        // release point before buffer (kt+1)&1 is overwritten.
    }
#undef ALOAD

    l0 += __shfl_xor_sync(0xffffffffu, l0, 1);
    l0 += __shfl_xor_sync(0xffffffffu, l0, 2);
    l1 += __shfl_xor_sync(0xffffffffu, l1, 1);
    l1 += __shfl_xor_sync(0xffffffffu, l1, 2);
    float inv0 = 1.f / l0, inv1 = 1.f / l1;

    // epilogue: write split hi/lo fp16 directly (consumed by O-projection)
#pragma unroll
    for (int nt = 0; nt < 16; nt++) {
        int col = head * HD + nt * 8 + cg * 2;
        if (qrow0 < LSEQ) {
            float v0 = oacc[nt][0] * inv0, v1 = oacc[nt][1] * inv0;
            __half h0 = __float2half_rn(v0), h1 = __float2half_rn(v1);
            size_t off = (size_t)qrow0 * DIM + col;
            *(uint32_t*)&ohi[off] = f2h2(v0, v1);
            *(uint32_t*)&olo[off] = f2h2(v0 - __half2float(h0), v1 - __half2float(h1));
        }
        if (qrow1 < LSEQ) {
            float v0 = oacc[nt][2] * inv1, v1 = oacc[nt][3] * inv1;
            __half h0 = __float2half_rn(v0), h1 = __float2half_rn(v1);
            size_t off = (size_t)qrow1 * DIM + col;
            *(uint32_t*)&ohi[off] = f2h2(v0, v1);
            *(uint32_t*)&olo[off] = f2h2(v0 - __half2float(h0), v1 - __half2float(h1));
        }
    }
}

// ---------------------------------------------------------------------------
extern "C" void kernel_launch(void* const* d_in, const int* in_sizes, int n_in,
                              void* d_out, int out_size)
{
    const float* x     = (const float*)d_in[0];
    const float* freqs = (const float*)d_in[1];
    const float* Wq    = (const float*)d_in[2];
    const float* bq    = (const float*)d_in[3];
    const float* Wk    = (const float*)d_in[4];
    const float* bk    = (const float*)d_in[5];
    const float* Wv    = (const float*)d_in[6];
    const float* bv    = (const float*)d_in[7];
    const float* Wo    = (const float*)d_in[8];
    const float* bo    = (const float*)d_in[9];
    const float* gq    = (const float*)d_in[10];
    const float* gk    = (const float*)d_in[11];
    const int* p_h     = (const int*)d_in[13];
    const int* p_w     = (const int*)d_in[14];
    const int* p_local = (const int*)d_in[16];
    const int* p_sink  = (const int*)d_in[17];
    const int* p_sf    = (const int*)d_in[18];
    float* out = (float*)d_out;
    (void)in_sizes; (void)n_in; (void)out_size;

    float *pq, *pk, *pv;
    cudaGetSymbolAddress((void**)&pq, g_q);
    cudaGetSymbolAddress((void**)&pk, g_k);
    cudaGetSymbolAddress((void**)&pv, g_v);

    __half *xhi, *xlo, *ohi, *olo;
    __half *wqhi, *wkhi, *wvhi, *wohi;
    __half *aqhi, *akhi, *vthi;
    cudaGetSymbolAddress((void**)&xhi, g_xhi);
    cudaGetSymbolAddress((void**)&xlo, g_xlo);
    cudaGetSymbolAddress((void**)&ohi, g_ohi);
    cudaGetSymbolAddress((void**)&olo, g_olo);
    cudaGetSymbolAddress((void**)&wqhi, g_wqhi);
    cudaGetSymbolAddress((void**)&wkhi, g_wkhi);
    cudaGetSymbolAddress((void**)&wvhi, g_wvhi);
    cudaGetSymbolAddress((void**)&wohi, g_wohi);
    cudaGetSymbolAddress((void**)&aqhi, g_qhi);
    cudaGetSymbolAddress((void**)&akhi, g_khi);
    cudaGetSymbolAddress((void**)&vthi, g_vthi);

    const int GEMM_SMEM = 2 * 24576;   // 48 KB
    const int ATTN_SMEM = 2 * 32768;   // 64 KB
    cudaFuncSetAttribute(gemm_mma, cudaFuncAttributeMaxDynamicSharedMemorySize, GEMM_SMEM);
    cudaFuncSetAttribute(attn_mma, cudaFuncAttributeMaxDynamicSharedMemorySize, ATTN_SMEM);

    const int nx2 = LSEQ * DIM / 2, nw2 = DIM * DIM / 2;
    split_kern<<<(nx2 + 255) / 256, 256>>>(x, xhi, xlo, nx2);
    split_hi4_kern<<<(4 * nw2 + 255) / 256, 256>>>(Wq, Wk, Wv, Wo,
                                                   wqhi, wkhi, wvhi, wohi, nw2);

    dim3 gg(DIM / 128, (LSEQ + 127) / 128);
    gemm_mma<<<gg, 256, GEMM_SMEM>>>(xhi, xlo, wqhi, bq, pq, LSEQ);
    gemm_mma<<<gg, 256, GEMM_SMEM>>>(xhi, xlo, wkhi, bk, pk, LSEQ);
    gemm_mma<<<gg, 256, GEMM_SMEM>>>(xhi, xlo, wvhi, bv, pv, LSEQ);

    norm_rope<<<LSEQ, 256>>>(pq, pk, aqhi, akhi, gq, gk, freqs,
                             p_h, p_w, p_sf);
    prep_vt<<<dim3((LSEQ + 31) / 32, DIM / 32), 256>>>(pv, vthi);

    attn_mma<<<dim3((LSEQ + 63) / 64, NH), 128, ATTN_SMEM>>>(
        aqhi, akhi, vthi, ohi, olo, p_h, p_w, p_local, p_sink);

    gemm_mma<<<gg, 256, GEMM_SMEM>>>(ohi, olo, wohi, bo, out, LSEQ);
}